// round 5
// baseline (speedup 1.0000x reference)
#include <cuda_runtime.h>
#include <cuda_bf16.h>
#include <cstdint>

// Problem constants (from reference)
#define N_PTS 50000
#define CH    64
#define KNN   16
#define NBR   3      // dilation branches (1,2,4)
#define NCLOUD 25
#define PTS_PER_CLOUD 2000
#define KMAX  64

#define NEG_BIG (-1e30f)

// Scratch (device globals -- allocation-free rule)
__device__ float g_K[NBR * N_PTS * CH];   // k = x @ Wk[b]
__device__ float g_V[NBR * N_PTS * CH];   // v = x @ Wv[b]
__device__ float g_pool[NCLOUD * CH];     // per-cloud max of x

// ---------------------------------------------------------------------------
// Kernel 1: K/V GEMMs.  grid = (ceil(N/64), 6)  [6 = 3 branches x {K,V}]
// block = 128 threads; each thread computes a 4-row x 8-col tile.
// ---------------------------------------------------------------------------
__global__ __launch_bounds__(128) void gemm_kv_kernel(
    const float* __restrict__ x,
    const float* __restrict__ Wv,
    const float* __restrict__ Wk)
{
    const int mat = blockIdx.y;          // 0..5
    const int b   = mat >> 1;
    const float* W   = (mat & 1) ? (Wv + b * CH * CH) : (Wk + b * CH * CH);
    float*       out = (mat & 1) ? (g_V + (size_t)b * N_PTS * CH)
                                 : (g_K + (size_t)b * N_PTS * CH);

    __shared__ float Ws[CH][CH];       // [k][c]
    __shared__ float xs[64][CH + 1];   // padded to kill bank conflicts

    const int tid  = threadIdx.x;
    const int row0 = blockIdx.x * 64;

    // Load weight matrix (4096 floats) via float4
    const float4* W4  = (const float4*)W;
    float4*       Ws4 = (float4*)&Ws[0][0];
    #pragma unroll
    for (int i = tid; i < CH * CH / 4; i += 128) Ws4[i] = W4[i];

    // Load x tile (64 rows x 64 ch), guarded for the tail block
    for (int i = tid; i < 64 * (CH / 4); i += 128) {
        int r  = i / (CH / 4);
        int c4 = i % (CH / 4);
        float4 v = make_float4(0.f, 0.f, 0.f, 0.f);
        if (row0 + r < N_PTS)
            v = ((const float4*)x)[(size_t)(row0 + r) * (CH / 4) + c4];
        xs[r][c4 * 4 + 0] = v.x;
        xs[r][c4 * 4 + 1] = v.y;
        xs[r][c4 * 4 + 2] = v.z;
        xs[r][c4 * 4 + 3] = v.w;
    }
    __syncthreads();

    const int cx = (tid & 7) * 8;      // column base (0..56)
    const int ry = (tid >> 3) * 4;     // row base    (0..60)

    float acc[4][8];
    #pragma unroll
    for (int r = 0; r < 4; r++)
        #pragma unroll
        for (int c = 0; c < 8; c++) acc[r][c] = 0.f;

    #pragma unroll 4
    for (int k = 0; k < CH; k++) {
        float4 wA = *(const float4*)&Ws[k][cx];
        float4 wB = *(const float4*)&Ws[k][cx + 4];
        float xr[4];
        #pragma unroll
        for (int r = 0; r < 4; r++) xr[r] = xs[ry + r][k];
        #pragma unroll
        for (int r = 0; r < 4; r++) {
            acc[r][0] = fmaf(xr[r], wA.x, acc[r][0]);
            acc[r][1] = fmaf(xr[r], wA.y, acc[r][1]);
            acc[r][2] = fmaf(xr[r], wA.z, acc[r][2]);
            acc[r][3] = fmaf(xr[r], wA.w, acc[r][3]);
            acc[r][4] = fmaf(xr[r], wB.x, acc[r][4]);
            acc[r][5] = fmaf(xr[r], wB.y, acc[r][5]);
            acc[r][6] = fmaf(xr[r], wB.z, acc[r][6]);
            acc[r][7] = fmaf(xr[r], wB.w, acc[r][7]);
        }
    }

    #pragma unroll
    for (int r = 0; r < 4; r++) {
        int row = row0 + ry + r;
        if (row < N_PTS) {
            float4* o = (float4*)(out + (size_t)row * CH + cx);
            o[0] = make_float4(acc[r][0], acc[r][1], acc[r][2], acc[r][3]);
            o[1] = make_float4(acc[r][4], acc[r][5], acc[r][6], acc[r][7]);
        }
    }
}

// ---------------------------------------------------------------------------
// Kernel 2: per-cloud channel-wise max pool.  grid = 25, block = 512
// thread -> channel (tid&63), segment (tid>>6): 8 segments x 250 rows
// ---------------------------------------------------------------------------
__global__ __launch_bounds__(512) void pool_kernel(const float* __restrict__ x)
{
    __shared__ float red[512];
    const int cloud = blockIdx.x;
    const int c   = threadIdx.x & 63;
    const int seg = threadIdx.x >> 6;
    const int base = cloud * PTS_PER_CLOUD + seg * (PTS_PER_CLOUD / 8);

    float m = NEG_BIG;
    #pragma unroll 4
    for (int i = 0; i < PTS_PER_CLOUD / 8; i++)
        m = fmaxf(m, x[(size_t)(base + i) * CH + c]);

    red[threadIdx.x] = m;
    __syncthreads();
    if (seg == 0) {
        #pragma unroll
        for (int s = 1; s < 8; s++) m = fmaxf(m, red[s * 64 + c]);
        g_pool[cloud * CH + c] = m;
    }
}

// ---------------------------------------------------------------------------
// Kernel 3: fused attention over all 3 dilation branches + pool-max + residual.
// One warp per node; lane handles channels (2*lane, 2*lane+1).
// Softmax note: q_i is constant per segment and cancels -> Wq never used.
// ---------------------------------------------------------------------------
__global__ __launch_bounds__(256) void edge_kernel(
    const float* __restrict__ x,
    const float* __restrict__ pos,
    const float* __restrict__ Wp,      // [3][3][64]
    const float* __restrict__ bp,      // [3][64]
    const int*   __restrict__ ei,      // edge_index row0 (src), length N*KMAX
    const int*   __restrict__ batch,
    float*       __restrict__ out)
{
    const int warp = (blockIdx.x * blockDim.x + threadIdx.x) >> 5;
    if (warp >= N_PTS) return;
    const int n    = warp;
    const int lane = threadIdx.x & 31;
    const int c0   = lane * 2;

    const float2 xv = *(const float2*)(x + (size_t)n * CH + c0);
    const float pix = pos[n * 3 + 0];
    const float piy = pos[n * 3 + 1];
    const float piz = pos[n * 3 + 2];

    const int* eiN = ei + (size_t)n * KMAX;

    float2 best = make_float2(NEG_BIG, NEG_BIG);

    #pragma unroll
    for (int b = 0; b < NBR; b++) {
        const int dil = 1 << b;   // 1, 2, 4

        const float* Wpb = Wp + b * 3 * CH;
        const float2 w0  = *(const float2*)(Wpb + 0 * CH + c0);
        const float2 w1  = *(const float2*)(Wpb + 1 * CH + c0);
        const float2 w2  = *(const float2*)(Wpb + 2 * CH + c0);
        const float2 bpv = *(const float2*)(bp + b * CH + c0);

        // lanes 0..15 stage neighbor indices + positions
        int   j   = 0;
        float pjx = 0.f, pjy = 0.f, pjz = 0.f;
        if (lane < KNN) {
            j   = eiN[lane * dil];
            pjx = pos[j * 3 + 0];
            pjy = pos[j * 3 + 1];
            pjz = pos[j * 3 + 2];
        }

        const float* Kb = g_K + (size_t)b * N_PTS * CH;
        const float* Vb = g_V + (size_t)b * N_PTS * CH;

        float2 s[KNN], wv[KNN];
        float2 m = make_float2(NEG_BIG, NEG_BIG);

        #pragma unroll
        for (int t = 0; t < KNN; t++) {
            const int   jt = __shfl_sync(0xffffffffu, j, t);
            const float dx = pix - __shfl_sync(0xffffffffu, pjx, t);
            const float dy = piy - __shfl_sync(0xffffffffu, pjy, t);
            const float dz = piz - __shfl_sync(0xffffffffu, pjz, t);

            const float2 kv = *(const float2*)(Kb + (size_t)jt * CH + c0);
            const float2 vv = *(const float2*)(Vb + (size_t)jt * CH + c0);

            float2 del;
            del.x = fmaf(dx, w0.x, fmaf(dy, w1.x, fmaf(dz, w2.x, bpv.x)));
            del.y = fmaf(dx, w0.y, fmaf(dy, w1.y, fmaf(dz, w2.y, bpv.y)));

            s[t].x  = del.x - kv.x;
            s[t].y  = del.y - kv.y;
            wv[t].x = vv.x + del.x;
            wv[t].y = vv.y + del.y;
            m.x = fmaxf(m.x, s[t].x);
            m.y = fmaxf(m.y, s[t].y);
        }

        float2 sum = make_float2(0.f, 0.f);
        float2 acc = make_float2(0.f, 0.f);
        #pragma unroll
        for (int t = 0; t < KNN; t++) {
            const float ex = __expf(s[t].x - m.x);
            const float ey = __expf(s[t].y - m.y);
            sum.x += ex;
            sum.y += ey;
            acc.x = fmaf(ex, wv[t].x, acc.x);
            acc.y = fmaf(ey, wv[t].y, acc.y);
        }

        const float hx = acc.x / (sum.x + 1e-16f);
        const float hy = acc.y / (sum.y + 1e-16f);
        best.x = fmaxf(best.x, hx);
        best.y = fmaxf(best.y, hy);
    }

    const int cloud = batch[n];
    const float2 p = *(const float2*)(g_pool + cloud * CH + c0);

    float2 o;
    o.x = fmaxf(best.x, p.x) + xv.x;
    o.y = fmaxf(best.y, p.y) + xv.y;
    *(float2*)(out + (size_t)n * CH + c0) = o;
}

// ---------------------------------------------------------------------------
// Launch.  Inputs (metadata order):
//  0: x[N*64] f32, 1: pos[N*3] f32, 2: Wv[3*64*64], 3: Wq (UNUSED),
//  4: Wk[3*64*64], 5: Wp[3*3*64], 6: bp[3*64],
//  7: edge_index[2*N*64] i32, 8: batch[N] i32
// ---------------------------------------------------------------------------
extern "C" void kernel_launch(void* const* d_in, const int* in_sizes, int n_in,
                              void* d_out, int out_size)
{
    (void)in_sizes; (void)n_in; (void)out_size;
    const float* x   = (const float*)d_in[0];
    const float* pos = (const float*)d_in[1];
    const float* Wv  = (const float*)d_in[2];
    const float* Wk  = (const float*)d_in[4];
    const float* Wp  = (const float*)d_in[5];
    const float* bp  = (const float*)d_in[6];
    const int*   ei  = (const int*)d_in[7];      // row0 = src
    const int*   bat = (const int*)d_in[8];
    float* out = (float*)d_out;

    dim3 ggrid((N_PTS + 63) / 64, 6);
    gemm_kv_kernel<<<ggrid, 128>>>(x, Wv, Wk);

    pool_kernel<<<NCLOUD, 512>>>(x);

    const int nwarps = N_PTS;
    const int blocks = (nwarps * 32 + 255) / 256;
    edge_kernel<<<blocks, 256>>>(x, pos, Wp, bp, ei, bat, out);
}

// round 6
// speedup vs baseline: 1.4512x; 1.4512x over previous
#include <cuda_runtime.h>
#include <cuda_fp16.h>
#include <cuda_bf16.h>
#include <cstdint>

// Problem constants (from reference)
#define N_PTS 50000
#define CH    64
#define KNN   16
#define NBR   3      // dilation branches (1,2,4)
#define NCLOUD 25
#define PTS_PER_CLOUD 2000
#define KMAX  64

#define NEG_BIG (-1e30f)

// Scratch (device globals -- allocation-free rule)
// Packed K/V: for node n, branch b, channel c: g_KV[(n*3+b)*64 + c] = half2(k, v)
__device__ __half2 g_KV[(size_t)N_PTS * NBR * CH];
__device__ float   g_pool[NCLOUD * CH];     // per-cloud max of x

// ---------------------------------------------------------------------------
// Kernel 1: fused K+V GEMM per branch.  grid = (ceil(N/64), 3)
// block = 128 threads; each thread computes a 4-row x 8-col tile of BOTH
// K = x@Wk[b] and V = x@Wv[b], then stores packed half2(k,v).
// ---------------------------------------------------------------------------
__global__ __launch_bounds__(128) void gemm_kv_kernel(
    const float* __restrict__ x,
    const float* __restrict__ Wv,
    const float* __restrict__ Wk)
{
    const int b = blockIdx.y;            // branch 0..2
    const float* WK = Wk + b * CH * CH;
    const float* WV = Wv + b * CH * CH;

    __shared__ float Wks[CH][CH];        // [k][c]
    __shared__ float Wvs[CH][CH];
    __shared__ float xs[64][CH + 1];     // padded

    const int tid  = threadIdx.x;
    const int row0 = blockIdx.x * 64;

    // Load both weight matrices (4096 floats each) via float4
    {
        const float4* a4 = (const float4*)WK;
        const float4* b4 = (const float4*)WV;
        float4* as4 = (float4*)&Wks[0][0];
        float4* bs4 = (float4*)&Wvs[0][0];
        #pragma unroll
        for (int i = tid; i < CH * CH / 4; i += 128) { as4[i] = a4[i]; bs4[i] = b4[i]; }
    }

    // Load x tile (64 rows x 64 ch), guarded for the tail block
    for (int i = tid; i < 64 * (CH / 4); i += 128) {
        int r  = i / (CH / 4);
        int c4 = i % (CH / 4);
        float4 v = make_float4(0.f, 0.f, 0.f, 0.f);
        if (row0 + r < N_PTS)
            v = ((const float4*)x)[(size_t)(row0 + r) * (CH / 4) + c4];
        xs[r][c4 * 4 + 0] = v.x;
        xs[r][c4 * 4 + 1] = v.y;
        xs[r][c4 * 4 + 2] = v.z;
        xs[r][c4 * 4 + 3] = v.w;
    }
    __syncthreads();

    const int cx = (tid & 7) * 8;      // column base (0..56)
    const int ry = (tid >> 3) * 4;     // row base    (0..60)

    float accK[4][8], accV[4][8];
    #pragma unroll
    for (int r = 0; r < 4; r++)
        #pragma unroll
        for (int c = 0; c < 8; c++) { accK[r][c] = 0.f; accV[r][c] = 0.f; }

    #pragma unroll 8
    for (int k = 0; k < CH; k++) {
        float4 kA = *(const float4*)&Wks[k][cx];
        float4 kB = *(const float4*)&Wks[k][cx + 4];
        float4 vA = *(const float4*)&Wvs[k][cx];
        float4 vB = *(const float4*)&Wvs[k][cx + 4];
        float xr[4];
        #pragma unroll
        for (int r = 0; r < 4; r++) xr[r] = xs[ry + r][k];
        #pragma unroll
        for (int r = 0; r < 4; r++) {
            accK[r][0] = fmaf(xr[r], kA.x, accK[r][0]);
            accK[r][1] = fmaf(xr[r], kA.y, accK[r][1]);
            accK[r][2] = fmaf(xr[r], kA.z, accK[r][2]);
            accK[r][3] = fmaf(xr[r], kA.w, accK[r][3]);
            accK[r][4] = fmaf(xr[r], kB.x, accK[r][4]);
            accK[r][5] = fmaf(xr[r], kB.y, accK[r][5]);
            accK[r][6] = fmaf(xr[r], kB.z, accK[r][6]);
            accK[r][7] = fmaf(xr[r], kB.w, accK[r][7]);
            accV[r][0] = fmaf(xr[r], vA.x, accV[r][0]);
            accV[r][1] = fmaf(xr[r], vA.y, accV[r][1]);
            accV[r][2] = fmaf(xr[r], vA.z, accV[r][2]);
            accV[r][3] = fmaf(xr[r], vA.w, accV[r][3]);
            accV[r][4] = fmaf(xr[r], vB.x, accV[r][4]);
            accV[r][5] = fmaf(xr[r], vB.y, accV[r][5]);
            accV[r][6] = fmaf(xr[r], vB.z, accV[r][6]);
            accV[r][7] = fmaf(xr[r], vB.w, accV[r][7]);
        }
    }

    #pragma unroll
    for (int r = 0; r < 4; r++) {
        int row = row0 + ry + r;
        if (row < N_PTS) {
            // Pack 8 channels of (k,v) into 8 half2 = 32 contiguous bytes
            uint32_t pk[8];
            #pragma unroll
            for (int c = 0; c < 8; c++) {
                __half2 h = __float22half2_rn(make_float2(accK[r][c], accV[r][c]));
                pk[c] = *(uint32_t*)&h;
            }
            __half2* dst = g_KV + ((size_t)row * NBR + b) * CH + cx;
            ((uint4*)dst)[0] = make_uint4(pk[0], pk[1], pk[2], pk[3]);
            ((uint4*)dst)[1] = make_uint4(pk[4], pk[5], pk[6], pk[7]);
        }
    }
}

// ---------------------------------------------------------------------------
// Kernel 2: per-cloud channel-wise max pool.  grid = 25, block = 1024
// thread -> channel (tid&63), segment (tid>>6): 16 segments x 125 rows
// ---------------------------------------------------------------------------
__global__ __launch_bounds__(1024) void pool_kernel(const float* __restrict__ x)
{
    __shared__ float red[1024];
    const int cloud = blockIdx.x;
    const int c   = threadIdx.x & 63;
    const int seg = threadIdx.x >> 6;
    const int base = cloud * PTS_PER_CLOUD + seg * (PTS_PER_CLOUD / 16);

    float m = NEG_BIG;
    #pragma unroll 5
    for (int i = 0; i < PTS_PER_CLOUD / 16; i++)
        m = fmaxf(m, x[(size_t)(base + i) * CH + c]);

    red[threadIdx.x] = m;
    __syncthreads();
    if (seg == 0) {
        #pragma unroll
        for (int s = 1; s < 16; s++) m = fmaxf(m, red[s * 64 + c]);
        g_pool[cloud * CH + c] = m;
    }
}

// ---------------------------------------------------------------------------
// Kernel 3: fused attention over all 3 dilation branches + pool-max + residual.
// One warp per node; lane handles channels (2*lane, 2*lane+1).
// Softmax note: q_i is constant per segment and cancels -> Wq never used.
// K/V gathered from packed half2(k,v) layout: one LDG.64 per (neighbor, 2ch).
// ---------------------------------------------------------------------------
__global__ __launch_bounds__(256) void edge_kernel(
    const float* __restrict__ x,
    const float* __restrict__ pos,
    const float* __restrict__ Wp,      // [3][3][64]
    const float* __restrict__ bp,      // [3][64]
    const int*   __restrict__ ei,      // edge_index row0 (src), length N*KMAX
    const int*   __restrict__ batch,
    float*       __restrict__ out)
{
    const int warp = (blockIdx.x * blockDim.x + threadIdx.x) >> 5;
    if (warp >= N_PTS) return;
    const int n    = warp;
    const int lane = threadIdx.x & 31;
    const int c0   = lane * 2;

    const float2 xv = *(const float2*)(x + (size_t)n * CH + c0);
    const float pix = pos[n * 3 + 0];
    const float piy = pos[n * 3 + 1];
    const float piz = pos[n * 3 + 2];

    const int* eiN = ei + (size_t)n * KMAX;

    float2 best = make_float2(NEG_BIG, NEG_BIG);

    #pragma unroll
    for (int b = 0; b < NBR; b++) {
        const int dil = 1 << b;   // 1, 2, 4

        const float* Wpb = Wp + b * 3 * CH;
        const float2 w0  = *(const float2*)(Wpb + 0 * CH + c0);
        const float2 w1  = *(const float2*)(Wpb + 1 * CH + c0);
        const float2 w2  = *(const float2*)(Wpb + 2 * CH + c0);
        const float2 bpv = *(const float2*)(bp + b * CH + c0);

        // lanes 0..15 stage neighbor indices + positions
        int   j   = 0;
        float pjx = 0.f, pjy = 0.f, pjz = 0.f;
        if (lane < KNN) {
            j   = eiN[lane * dil];
            pjx = pos[j * 3 + 0];
            pjy = pos[j * 3 + 1];
            pjz = pos[j * 3 + 2];
        }

        float2 s[KNN], wv[KNN];
        float2 m = make_float2(NEG_BIG, NEG_BIG);

        #pragma unroll
        for (int t = 0; t < KNN; t++) {
            const int   jt = __shfl_sync(0xffffffffu, j, t);
            const float dx = pix - __shfl_sync(0xffffffffu, pjx, t);
            const float dy = piy - __shfl_sync(0xffffffffu, pjy, t);
            const float dz = piz - __shfl_sync(0xffffffffu, pjz, t);

            // one 8B load fetches (k,v) for both channels
            const uint2 raw = *(const uint2*)(g_KV + ((size_t)jt * NBR + b) * CH + c0);
            const float2 kv0 = __half22float2(*(const __half2*)&raw.x);  // (k,v) @ c0
            const float2 kv1 = __half22float2(*(const __half2*)&raw.y);  // (k,v) @ c0+1

            float2 del;
            del.x = fmaf(dx, w0.x, fmaf(dy, w1.x, fmaf(dz, w2.x, bpv.x)));
            del.y = fmaf(dx, w0.y, fmaf(dy, w1.y, fmaf(dz, w2.y, bpv.y)));

            s[t].x  = del.x - kv0.x;
            s[t].y  = del.y - kv1.x;
            wv[t].x = kv0.y + del.x;
            wv[t].y = kv1.y + del.y;
            m.x = fmaxf(m.x, s[t].x);
            m.y = fmaxf(m.y, s[t].y);
        }

        float2 sum = make_float2(0.f, 0.f);
        float2 acc = make_float2(0.f, 0.f);
        #pragma unroll
        for (int t = 0; t < KNN; t++) {
            const float ex = __expf(s[t].x - m.x);
            const float ey = __expf(s[t].y - m.y);
            sum.x += ex;
            sum.y += ey;
            acc.x = fmaf(ex, wv[t].x, acc.x);
            acc.y = fmaf(ey, wv[t].y, acc.y);
        }

        const float hx = acc.x / (sum.x + 1e-16f);
        const float hy = acc.y / (sum.y + 1e-16f);
        best.x = fmaxf(best.x, hx);
        best.y = fmaxf(best.y, hy);
    }

    const int cloud = batch[n];
    const float2 p = *(const float2*)(g_pool + cloud * CH + c0);

    float2 o;
    o.x = fmaxf(best.x, p.x) + xv.x;
    o.y = fmaxf(best.y, p.y) + xv.y;
    *(float2*)(out + (size_t)n * CH + c0) = o;
}

// ---------------------------------------------------------------------------
// Launch.  Inputs (metadata order):
//  0: x[N*64] f32, 1: pos[N*3] f32, 2: Wv[3*64*64], 3: Wq (UNUSED),
//  4: Wk[3*64*64], 5: Wp[3*3*64], 6: bp[3*64],
//  7: edge_index[2*N*64] i32, 8: batch[N] i32
// ---------------------------------------------------------------------------
extern "C" void kernel_launch(void* const* d_in, const int* in_sizes, int n_in,
                              void* d_out, int out_size)
{
    (void)in_sizes; (void)n_in; (void)out_size;
    const float* x   = (const float*)d_in[0];
    const float* pos = (const float*)d_in[1];
    const float* Wv  = (const float*)d_in[2];
    const float* Wk  = (const float*)d_in[4];
    const float* Wp  = (const float*)d_in[5];
    const float* bp  = (const float*)d_in[6];
    const int*   ei  = (const int*)d_in[7];      // row0 = src
    const int*   bat = (const int*)d_in[8];
    float* out = (float*)d_out;

    dim3 ggrid((N_PTS + 63) / 64, NBR);
    gemm_kv_kernel<<<ggrid, 128>>>(x, Wv, Wk);

    pool_kernel<<<NCLOUD, 1024>>>(x);

    const int nwarps = N_PTS;
    const int blocks = (nwarps * 32 + 255) / 256;
    edge_kernel<<<blocks, 256>>>(x, pos, Wp, bp, ei, bat, out);
}